// round 12
// baseline (speedup 1.0000x reference)
#include <cuda_runtime.h>
#include <cstdint>

// ---------------- problem constants ----------------
#define B_    8
#define K_    8
#define C_    256
#define L_    4096
#define TOPK  4
#define KTOT  1024
#define BM    128
#define BN    64
#define BK    64
#define NCHUNK (KTOT / BK)     // 16

// ---------------- smem layout (bytes from dynamic smem base) ----------------
// Single buffer; phases are barrier-serialized, 2 CTAs/SM give the overlap.
// A tile: 128 rows x 64 bf16, padded row stride 72 bf16 = 144 B (9x16B odd -> ldmatrix conflict-free)
// B tile: 64 k-rows x 64 bf16, padded stride 144 B
#define ASTRIDE_B 144
#define BSTRIDE_B 144
#define ATILE_B   (128 * ASTRIDE_B)           // 18432
#define BTILE_B   (64 * BSTRIDE_B)            // 9216
#define OFF_AHI   0
#define OFF_ALO   ATILE_B
#define OFF_BHI   (2 * ATILE_B)
#define OFF_BLO   (2 * ATILE_B + BTILE_B)
#define SMEM_DYN  (2 * ATILE_B + 2 * BTILE_B) // 55296 -> 2 CTAs/SM

// ---------------- pre-converted weights (hi/lo bf16, 1 MB each) ----------------
__device__ uint16_t g_whi[K_ * C_ * C_];
__device__ uint16_t g_wlo[K_ * C_ * C_];

// ---------------- helpers ----------------
__device__ __forceinline__ uint32_t smem_u32(const void* p) {
    uint32_t a;
    asm("{ .reg .u64 t; cvta.to.shared.u64 t, %1; cvt.u32.u64 %0, t; }" : "=r"(a) : "l"(p));
    return a;
}

// split x -> (hi = truncate-to-bf16, lo = rn-bf16(x - hi)); pack two elements
__device__ __forceinline__ void split_pair(float x0, float x1,
                                           uint32_t& hi, uint32_t& lo) {
    uint32_t u0 = __float_as_uint(x0), u1 = __float_as_uint(x1);
    hi = __byte_perm(u0, u1, 0x7632);   // {bf16(x1)|bf16(x0)} truncated
    float l0 = x0 - __uint_as_float(u0 & 0xFFFF0000u);
    float l1 = x1 - __uint_as_float(u1 & 0xFFFF0000u);
    asm("cvt.rn.bf16x2.f32 %0, %1, %2;" : "=r"(lo) : "f"(l1), "f"(l0));
}

#define STS64(addr, r0, r1) \
    asm volatile("st.shared.v2.b32 [%0], {%1, %2};" :: "r"(addr), "r"(r0), "r"(r1) : "memory")
#define STS128(addr, r0, r1, r2, r3) \
    asm volatile("st.shared.v4.b32 [%0], {%1, %2, %3, %4};" \
                 :: "r"(addr), "r"(r0), "r"(r1), "r"(r2), "r"(r3) : "memory")

__device__ __forceinline__ void ldsm_x4(uint32_t addr, uint32_t* r) {
    asm volatile("ldmatrix.sync.aligned.m8n8.x4.shared.b16 {%0,%1,%2,%3}, [%4];"
                 : "=r"(r[0]), "=r"(r[1]), "=r"(r[2]), "=r"(r[3]) : "r"(addr));
}
__device__ __forceinline__ void ldsm_x2_trans(uint32_t addr, uint32_t* r) {
    asm volatile("ldmatrix.sync.aligned.m8n8.x2.trans.shared.b16 {%0,%1}, [%2];"
                 : "=r"(r[0]), "=r"(r[1]) : "r"(addr));
}
__device__ __forceinline__ void mma_bf16(float* c, const uint32_t* a, const uint32_t* bfr) {
    asm volatile(
        "mma.sync.aligned.m16n8k16.row.col.f32.bf16.bf16.f32 "
        "{%0,%1,%2,%3}, {%4,%5,%6,%7}, {%8,%9}, {%0,%1,%2,%3};"
        : "+f"(c[0]), "+f"(c[1]), "+f"(c[2]), "+f"(c[3])
        : "r"(a[0]), "r"(a[1]), "r"(a[2]), "r"(a[3]), "r"(bfr[0]), "r"(bfr[1]));
}

// ---------------- routing globals ----------------
__device__ int   g_sel[B_][TOPK];
__device__ float g_w[B_][TOPK];
__device__ float g_bias[B_][C_];

__global__ void prep_kernel(const float* __restrict__ scores,
                            const float* __restrict__ expert_b) {
    __shared__ int   s_sel[B_][TOPK];
    __shared__ float s_w[B_][TOPK];
    const int tid = threadIdx.x;
    if (tid < B_) {
        const int b = tid;
        float sc[K_]; bool used[K_];
#pragma unroll
        for (int k = 0; k < K_; k++) { sc[k] = scores[b * K_ + k]; used[k] = false; }
        float sum = 0.f;
#pragma unroll
        for (int j = 0; j < TOPK; j++) {
            int best = 0; float bv = -3.402823466e+38f;
#pragma unroll
            for (int k = 0; k < K_; k++)
                if (!used[k] && sc[k] > bv) { bv = sc[k]; best = k; }  // ties -> lower idx
            used[best] = true; s_sel[b][j] = best; s_w[b][j] = bv; sum += bv;
        }
        const float inv = 1.f / (sum + 1e-8f);
#pragma unroll
        for (int j = 0; j < TOPK; j++) {
            s_w[b][j] *= inv; g_sel[b][j] = s_sel[b][j]; g_w[b][j] = s_w[b][j];
        }
    }
    __syncthreads();
    for (int idx = tid; idx < B_ * C_; idx += blockDim.x) {
        const int b = idx / C_, d = idx % C_;
        float acc = 0.f;
#pragma unroll
        for (int j = 0; j < TOPK; j++)
            acc += s_w[b][j] * expert_b[s_sel[b][j] * C_ + d];
        g_bias[b][d] = acc;
    }
}

// one-shot: split expert_w into hi/lo bf16 (pairs along contiguous c)
__global__ void convert_w_kernel(const float* __restrict__ expert_w) {
    const int npairs = K_ * C_ * C_ / 2;           // 262144
    uint32_t* whi = (uint32_t*)g_whi;
    uint32_t* wlo = (uint32_t*)g_wlo;
    for (int p = blockIdx.x * blockDim.x + threadIdx.x; p < npairs;
         p += gridDim.x * blockDim.x) {
        float2 v = *(const float2*)(expert_w + (size_t)p * 2);
        uint32_t hi, lo;
        split_pair(v.x, v.y, hi, lo);
        whi[p] = hi;
        wlo[p] = lo;
    }
}

// ---------------------------------------------------------------------------
// Tensor-core MoE GEMM via mma.sync (bf16 hi/lo split, 3 terms, fp32 accum).
// A (weights) pre-converted to bf16 hi/lo -> pure LDG/STS stage, no ALU.
// Combine weight w_j applied on B (xs) during its split.
// out[b](256x4096) = sum_j W_sel_j @ (w_j * xs_j) + bias
// ---------------------------------------------------------------------------
__global__ __launch_bounds__(256, 2)
void moe_mma_kernel(const float* __restrict__ xs,
                    float* __restrict__ out) {
    extern __shared__ char smem[];
    const uint32_t sb = smem_u32(smem);

    const int tid  = threadIdx.x;
    const int wid  = tid >> 5;
    const int lane = tid & 31;
    const int b    = blockIdx.z;
    const int m0   = blockIdx.y * BM;
    const int n0   = blockIdx.x * BN;

    int   sel[TOPK];
    float wv[TOPK];
#pragma unroll
    for (int j = 0; j < TOPK; j++) { sel[j] = g_sel[b][j]; wv[j] = g_w[b][j]; }

    // warp tile: 32 (m) x 32 (n); 8 warps cover 128x64
    const int wm = wid >> 1, wn = wid & 1;
    const int m_base = wm * 32, n_base = wn * 32;

    float acc[2][4][4];
#pragma unroll
    for (int mi = 0; mi < 2; mi++)
#pragma unroll
        for (int ni = 0; ni < 4; ni++)
#pragma unroll
            for (int r = 0; r < 4; r++) acc[mi][ni][r] = 0.f;

    // ldmatrix address components
    const int lr = lane & 7;
    const int lg = lane >> 3;
    const int a_r_off = (lg & 1) * 8 + lr;
    const int a_c_off = (lg >> 1) * 8;
    const int b_r_off = (lg & 1) * 8 + lr;

    const uint32_t ah = sb + OFF_AHI, al = sb + OFF_ALO;
    const uint32_t bh = sb + OFF_BHI, bl = sb + OFF_BLO;

    // stage chunk ck (64 K-cols) into the single buffer
    auto stage_chunk = [&](int ck) {
        const int j  = ck >> 2;              // 4 chunks per expert (256/64)
        const int c0 = (ck & 3) * BK;
        const float wj = wv[j];
        const size_t abase = ((size_t)sel[j] * C_ + m0) * C_ + c0;
        const uint16_t* ahsrc = g_whi + abase;
        const uint16_t* alsrc = g_wlo + abase;
        const float* bsrc = xs + (((size_t)b * K_ + sel[j]) * C_ + c0) * L_ + n0;

        // A: bf16 hi/lo direct copy. 128 rows x 8 16B-xfers -> 4 per thread each
#pragma unroll
        for (int q = 0; q < 4; q++) {
            int f = q * 256 + tid;
            int r = f >> 3, c8 = f & 7;            // row, 16B-unit within 64 cols
            const size_t off = (size_t)r * C_ + c8 * 8;
            uint4 vh = *(const uint4*)(ahsrc + off);
            uint4 vl = *(const uint4*)(alsrc + off);
            uint32_t addr = r * ASTRIDE_B + c8 * 16;
            STS128(ah + addr, vh.x, vh.y, vh.z, vh.w);
            STS128(al + addr, vl.x, vl.y, vl.z, vl.w);
        }
        // B: fp32 -> scaled hi/lo split. 64 k-rows x 16 float4 -> 4 per thread
#pragma unroll
        for (int q = 0; q < 4; q++) {
            int f = q * 256 + tid;
            int r = f >> 4, c4 = f & 15;
            float4 v = *(const float4*)(bsrc + (size_t)r * L_ + c4 * 4);
            uint32_t h0, l0, h1, l1;
            split_pair(v.x * wj, v.y * wj, h0, l0);
            split_pair(v.z * wj, v.w * wj, h1, l1);
            uint32_t addr = r * BSTRIDE_B + c4 * 8;
            STS64(bh + addr, h0, h1);
            STS64(bl + addr, l0, l1);
        }
    };

    auto compute = [&]() {
#pragma unroll
        for (int ks = 0; ks < 4; ks++) {
            const int k0 = ks * 16;
            uint32_t Ah[2][4], Al[2][4], Bh[4][2], Bl[4][2];
#pragma unroll
            for (int mi = 0; mi < 2; mi++) {
                uint32_t addr = (m_base + mi * 16 + a_r_off) * ASTRIDE_B
                              + (k0 + a_c_off) * 2;
                ldsm_x4(ah + addr, Ah[mi]);
                ldsm_x4(al + addr, Al[mi]);
            }
#pragma unroll
            for (int ni = 0; ni < 4; ni++) {
                uint32_t addr = (k0 + b_r_off) * BSTRIDE_B
                              + (n_base + ni * 8) * 2;
                ldsm_x2_trans(bh + addr, Bh[ni]);
                ldsm_x2_trans(bl + addr, Bl[ni]);
            }
#pragma unroll
            for (int mi = 0; mi < 2; mi++)
#pragma unroll
                for (int ni = 0; ni < 4; ni++) {
                    mma_bf16(acc[mi][ni], Ah[mi], Bh[ni]);
                    mma_bf16(acc[mi][ni], Ah[mi], Bl[ni]);
                    mma_bf16(acc[mi][ni], Al[mi], Bh[ni]);
                }
        }
    };

    // ---- stage/compute loop, single buffer ----
    for (int ck = 0; ck < NCHUNK; ck++) {
        stage_chunk(ck);
        __syncthreads();
        compute();
        __syncthreads();
    }

    // ---- epilogue: + bias, write ----
    const int g  = lane >> 2;
    const int tq = lane & 3;
#pragma unroll
    for (int mi = 0; mi < 2; mi++) {
        const int r0 = m0 + m_base + mi * 16 + g;
        const int r1 = r0 + 8;
        const float bias0 = g_bias[b][r0];
        const float bias1 = g_bias[b][r1];
        float* p0 = out + ((size_t)b * C_ + r0) * L_ + n0 + n_base + tq * 2;
        float* p1 = out + ((size_t)b * C_ + r1) * L_ + n0 + n_base + tq * 2;
#pragma unroll
        for (int ni = 0; ni < 4; ni++) {
            float2 v0 = make_float2(acc[mi][ni][0] + bias0, acc[mi][ni][1] + bias0);
            float2 v1 = make_float2(acc[mi][ni][2] + bias1, acc[mi][ni][3] + bias1);
            *(float2*)(p0 + ni * 8) = v0;
            *(float2*)(p1 + ni * 8) = v1;
        }
    }
}

// ---------------- launch ----------------
extern "C" void kernel_launch(void* const* d_in, const int* in_sizes, int n_in,
                              void* d_out, int out_size) {
    const float* xs       = (const float*)d_in[0];
    const float* scores   = (const float*)d_in[1];
    const float* expert_w = (const float*)d_in[2];
    const float* expert_b = (const float*)d_in[3];
    float* out = (float*)d_out;

    cudaFuncSetAttribute(moe_mma_kernel,
                         cudaFuncAttributeMaxDynamicSharedMemorySize, SMEM_DYN);

    prep_kernel<<<1, 256>>>(scores, expert_b);
    convert_w_kernel<<<256, 256>>>(expert_w);

    dim3 grid(L_ / BN, C_ / BM, B_);   // (64, 2, 8) = 1024 blocks
    moe_mma_kernel<<<grid, 256, SMEM_DYN>>>(xs, out);
}